// round 17
// baseline (speedup 1.0000x reference)
#include <cuda_runtime.h>
#include <cuda_bf16.h>
#include <math.h>
#include <stdint.h>

#define B_  2
#define T_  2048
#define DM  2048
#define NH  16
#define HD  128
#define NROWS (B_ * T_)   // 4096

// ---------------- scratch (no runtime allocation allowed) ----------------
__device__ float g_Q[(size_t)NROWS * DM];
__device__ float g_K[(size_t)NROWS * DM];
__device__ float g_V[(size_t)NROWS * DM];
__device__ float g_A[(size_t)NROWS * DM];
__device__ float g_xc[(size_t)NROWS * DM];
__device__ float g_Wc[4][(size_t)DM * DM];
__device__ unsigned short g_Qhi[(size_t)NROWS * DM];
__device__ unsigned short g_Qlo[(size_t)NROWS * DM];
__device__ unsigned short g_Khi[(size_t)NROWS * DM];
__device__ unsigned short g_Klo[(size_t)NROWS * DM];
__device__ unsigned short g_Vhi[(size_t)NROWS * DM];
__device__ unsigned short g_Vlo[(size_t)NROWS * DM];

__device__ __forceinline__ uint32_t f2tf32(float x) {
    uint32_t r;
    asm("cvt.rna.tf32.f32 %0, %1;" : "=r"(r) : "f"(x));
    return r;
}
__device__ __forceinline__ float tf32f(float x) { return __uint_as_float(f2tf32(x)); }

__device__ __forceinline__ uint32_t smem_u32(const void* p) {
    uint32_t a;
    asm("{ .reg .u64 t; cvta.to.shared.u64 t, %1; cvt.u32.u64 %0, t; }" : "=r"(a) : "l"(p));
    return a;
}

__device__ __forceinline__ void mma_tf32_16n8k8(float c[4], const uint32_t a[4],
                                                const uint32_t b0, const uint32_t b1) {
    asm volatile(
        "mma.sync.aligned.m16n8k8.row.col.f32.tf32.tf32.f32 "
        "{%0,%1,%2,%3}, {%4,%5,%6,%7}, {%8,%9}, {%0,%1,%2,%3};"
        : "+f"(c[0]), "+f"(c[1]), "+f"(c[2]), "+f"(c[3])
        : "r"(a[0]), "r"(a[1]), "r"(a[2]), "r"(a[3]), "r"(b0), "r"(b1));
}

__device__ __forceinline__ void mma_bf16_16n8k16(float c[4], const uint32_t a[4],
                                                 const uint32_t b0, const uint32_t b1) {
    asm volatile(
        "mma.sync.aligned.m16n8k16.row.col.f32.bf16.bf16.f32 "
        "{%0,%1,%2,%3}, {%4,%5,%6,%7}, {%8,%9}, {%0,%1,%2,%3};"
        : "+f"(c[0]), "+f"(c[1]), "+f"(c[2]), "+f"(c[3])
        : "r"(a[0]), "r"(a[1]), "r"(a[2]), "r"(a[3]), "r"(b0), "r"(b1));
}

__device__ __forceinline__ void bf16_split2(float x, float y, uint32_t& hi, uint32_t& lo) {
    __nv_bfloat16 hx = __float2bfloat16(x);
    __nv_bfloat16 hy = __float2bfloat16(y);
    __nv_bfloat16 lx = __float2bfloat16(x - __bfloat162float(hx));
    __nv_bfloat16 ly = __float2bfloat16(y - __bfloat162float(hy));
    hi = (uint32_t)__bfloat16_as_ushort(hx) | ((uint32_t)__bfloat16_as_ushort(hy) << 16);
    lo = (uint32_t)__bfloat16_as_ushort(lx) | ((uint32_t)__bfloat16_as_ushort(ly) << 16);
}

#define LDSM_X4(r0, r1, r2, r3, addr) \
    asm volatile("ldmatrix.sync.aligned.m8n8.x4.shared.b16 {%0,%1,%2,%3}, [%4];" \
                 : "=r"(r0), "=r"(r1), "=r"(r2), "=r"(r3) : "r"(addr))

#define LDSM_X4_T(r0, r1, r2, r3, addr) \
    asm volatile("ldmatrix.sync.aligned.m8n8.x4.trans.shared.b16 {%0,%1,%2,%3}, [%4];" \
                 : "=r"(r0), "=r"(r1), "=r"(r2), "=r"(r3) : "r"(addr))

#define CP_ASYNC16(sp, gp) \
    asm volatile("cp.async.cg.shared.global [%0], [%1], 16;" :: "r"(sp), "l"(gp))

// ==== tf32 round + k-permute, batched over x (2 halves) + 4 weights ======
__global__ __launch_bounds__(256) void cvt_all(const float* __restrict__ x,
                                               const float* __restrict__ w0,
                                               const float* __restrict__ w1,
                                               const float* __restrict__ w2,
                                               const float* __restrict__ w3,
                                               float* __restrict__ xout,
                                               float* __restrict__ wout, int ngroups) {
    int z = blockIdx.z;
    const float* in;
    float* out;
    if (z < 2) {
        in = x + (size_t)z * ngroups * 16;
        out = xout + (size_t)z * ngroups * 16;
    } else {
        int w = z - 2;
        in = (w == 0) ? w0 : (w == 1) ? w1 : (w == 2) ? w2 : w3;
        out = wout + (size_t)w * DM * DM;
    }
    int i = blockIdx.x * 256 + threadIdx.x;
    if (i < ngroups) {
        const float4* ip = (const float4*)(in + (size_t)i * 16);
        float4 v0 = ip[0], v1 = ip[1], v2 = ip[2], v3 = ip[3];
        float4* op = (float4*)(out + (size_t)i * 16);
        op[0] = make_float4(tf32f(v0.x), tf32f(v1.x), tf32f(v2.x), tf32f(v3.x));
        op[1] = make_float4(tf32f(v0.y), tf32f(v1.y), tf32f(v2.y), tf32f(v3.y));
        op[2] = make_float4(tf32f(v0.z), tf32f(v1.z), tf32f(v2.z), tf32f(v3.z));
        op[3] = make_float4(tf32f(v0.w), tf32f(v1.w), tf32f(v2.w), tf32f(v3.w));
    }
}

// ======== fused RoPE + bf16 hi/lo split of Q (scaled), K, V ==============
__global__ __launch_bounds__(256) void rope_split(const float* __restrict__ Q,
                                                  const float* __restrict__ K,
                                                  const float* __restrict__ V,
                                                  unsigned short* __restrict__ Qhi_g,
                                                  unsigned short* __restrict__ Qlo_g,
                                                  unsigned short* __restrict__ Khi_g,
                                                  unsigned short* __restrict__ Klo_g,
                                                  unsigned short* __restrict__ Vhi_g,
                                                  unsigned short* __restrict__ Vlo_g) {
    const float scale = 0.08838834764831845f;
    const float LOG2_10000 = 13.287712379549449f;
    int idx = blockIdx.x * 256 + threadIdx.x;
    int d4 = (idx & 15) * 4;
    int h = (idx >> 4) & (NH - 1);
    int n = idx >> 8;
    int t = n & (T_ - 1);
    size_t base = (size_t)n * DM + h * HD;

    float c[4], s[4];
#pragma unroll
    for (int j = 0; j < 4; j++) {
        float inv = exp2f(-(float)(2 * (d4 + j)) * (LOG2_10000 / 128.0f));
        sincosf((float)t * inv, &s[j], &c[j]);
    }

    uint32_t h0, l0, h1, l1;
    {
        float4 q1 = *(const float4*)(Q + base + d4);
        float4 q2 = *(const float4*)(Q + base + d4 + 64);
        float a0 = (q1.x * c[0] - q2.x * s[0]) * scale;
        float a1 = (q1.y * c[1] - q2.y * s[1]) * scale;
        float a2 = (q1.z * c[2] - q2.z * s[2]) * scale;
        float a3 = (q1.w * c[3] - q2.w * s[3]) * scale;
        float b0 = (q2.x * c[0] + q1.x * s[0]) * scale;
        float b1 = (q2.y * c[1] + q1.y * s[1]) * scale;
        float b2 = (q2.z * c[2] + q1.z * s[2]) * scale;
        float b3 = (q2.w * c[3] + q1.w * s[3]) * scale;
        bf16_split2(a0, a1, h0, l0); bf16_split2(a2, a3, h1, l1);
        *(uint2*)(Qhi_g + base + d4) = make_uint2(h0, h1);
        *(uint2*)(Qlo_g + base + d4) = make_uint2(l0, l1);
        bf16_split2(b0, b1, h0, l0); bf16_split2(b2, b3, h1, l1);
        *(uint2*)(Qhi_g + base + d4 + 64) = make_uint2(h0, h1);
        *(uint2*)(Qlo_g + base + d4 + 64) = make_uint2(l0, l1);
    }
    {
        float4 k1 = *(const float4*)(K + base + d4);
        float4 k2 = *(const float4*)(K + base + d4 + 64);
        float a0 = k1.x * c[0] - k2.x * s[0];
        float a1 = k1.y * c[1] - k2.y * s[1];
        float a2 = k1.z * c[2] - k2.z * s[2];
        float a3 = k1.w * c[3] - k2.w * s[3];
        float b0 = k2.x * c[0] + k1.x * s[0];
        float b1 = k2.y * c[1] + k1.y * s[1];
        float b2 = k2.z * c[2] + k1.z * s[2];
        float b3 = k2.w * c[3] + k1.w * s[3];
        bf16_split2(a0, a1, h0, l0); bf16_split2(a2, a3, h1, l1);
        *(uint2*)(Khi_g + base + d4) = make_uint2(h0, h1);
        *(uint2*)(Klo_g + base + d4) = make_uint2(l0, l1);
        bf16_split2(b0, b1, h0, l0); bf16_split2(b2, b3, h1, l1);
        *(uint2*)(Khi_g + base + d4 + 64) = make_uint2(h0, h1);
        *(uint2*)(Klo_g + base + d4 + 64) = make_uint2(l0, l1);
    }
    {
        float4 v1 = *(const float4*)(V + base + d4);
        float4 v2 = *(const float4*)(V + base + d4 + 64);
        bf16_split2(v1.x, v1.y, h0, l0); bf16_split2(v1.z, v1.w, h1, l1);
        *(uint2*)(Vhi_g + base + d4) = make_uint2(h0, h1);
        *(uint2*)(Vlo_g + base + d4) = make_uint2(l0, l1);
        bf16_split2(v2.x, v2.y, h0, l0); bf16_split2(v2.z, v2.w, h1, l1);
        *(uint2*)(Vhi_g + base + d4 + 64) = make_uint2(h0, h1);
        *(uint2*)(Vlo_g + base + d4 + 64) = make_uint2(l0, l1);
    }
}

// == TF32 mma GEMM (R9 config): 128 thr, 4 warps (2x2), warp 64x64, 3-stage ==
#define GK 2048
#define GN 2048
#define CSTAGE_F (2 * 128 * 32)
#define GEMM_SMEM (3 * CSTAGE_F * 4)

__device__ __forceinline__ uint32_t sw_word(int row, int chunk) {
    return (uint32_t)(row * 32 + ((chunk ^ ((row & 1) << 2)) << 2));
}

__global__ __launch_bounds__(128) void gemm_perm(const float* __restrict__ A,
                                                 const float* __restrict__ B0, float* __restrict__ C0,
                                                 const float* __restrict__ B1, float* __restrict__ C1,
                                                 const float* __restrict__ B2, float* __restrict__ C2) {
    extern __shared__ float sh[];
    const int z = blockIdx.z;
    const float* Bm = (z == 0) ? B0 : (z == 1) ? B1 : B2;
    float* C = (z == 0) ? C0 : (z == 1) ? C1 : C2;
    const int tid = threadIdx.x;
    const int warp = tid >> 5;
    const int lane = tid & 31;
    const int g = lane >> 2;
    const int t = lane & 3;
    const int warp_m = warp & 1;
    const int warp_n = warp >> 1;
    const int m0 = blockIdx.y * 128;
    const int n0 = blockIdx.x * 128;
    const uint32_t sbase = smem_u32(sh);

    float acc[4][8][4];
#pragma unroll
    for (int mt = 0; mt < 4; mt++)
#pragma unroll
        for (int nt = 0; nt < 8; nt++)
#pragma unroll
            for (int j = 0; j < 4; j++) acc[mt][nt][j] = 0.f;

    const int NIT = GK / 32;

#define GEMM_ISSUE(stage, k0)                                                      \
    do {                                                                           \
        const uint32_t stb = sbase + (stage) * CSTAGE_F * 4;                       \
        _Pragma("unroll")                                                          \
        for (int i_ = 0; i_ < 16; i_++) {                                          \
            int idx = i_ * 128 + tid;                                              \
            int mat = idx >> 10;                                                   \
            int r = (idx >> 3) & 127;                                              \
            int ch = idx & 7;                                                      \
            const float* gp = (mat ? Bm + (size_t)(n0 + r) * GK                    \
                                   : A + (size_t)(m0 + r) * GK) + (k0) + ch * 4;   \
            uint32_t sp = stb + (mat * 128 * 32 + sw_word(r, ch)) * 4;             \
            CP_ASYNC16(sp, gp);                                                    \
        }                                                                          \
        asm volatile("cp.async.commit_group;" ::: "memory");                       \
    } while (0)

    GEMM_ISSUE(0, 0);
    GEMM_ISSUE(1, 32);

    for (int it = 0; it < NIT; it++) {
        if (it + 1 < NIT) asm volatile("cp.async.wait_group 1;" ::: "memory");
        else              asm volatile("cp.async.wait_group 0;" ::: "memory");
        __syncthreads();

        const float* As = sh + (it % 3) * CSTAGE_F;
        const float* Bs = As + 128 * 32;
#pragma unroll
        for (int ks2 = 0; ks2 < 2; ks2++) {
            const int c0 = 4 * ks2 + t;
            float4 alo[4], ahi[4];
#pragma unroll
            for (int mt = 0; mt < 4; mt++) {
                int r0 = warp_m * 64 + mt * 16 + g;
                alo[mt] = *(const float4*)&As[sw_word(r0, c0)];
                ahi[mt] = *(const float4*)&As[sw_word(r0 + 8, c0)];
            }
            float4 bv[8];
#pragma unroll
            for (int nt = 0; nt < 8; nt++) {
                int cn = warp_n * 64 + nt * 8 + g;
                bv[nt] = *(const float4*)&Bs[sw_word(cn, c0)];
            }
#pragma unroll
            for (int mt = 0; mt < 4; mt++) {
                uint32_t af[4] = {__float_as_uint(alo[mt].x), __float_as_uint(ahi[mt].x),
                                  __float_as_uint(alo[mt].y), __float_as_uint(ahi[mt].y)};
#pragma unroll
                for (int nt = 0; nt < 8; nt++)
                    mma_tf32_16n8k8(acc[mt][nt], af,
                                    __float_as_uint(bv[nt].x), __float_as_uint(bv[nt].y));
            }
#pragma unroll
            for (int mt = 0; mt < 4; mt++) {
                uint32_t af[4] = {__float_as_uint(alo[mt].z), __float_as_uint(ahi[mt].z),
                                  __float_as_uint(alo[mt].w), __float_as_uint(ahi[mt].w)};
#pragma unroll
                for (int nt = 0; nt < 8; nt++)
                    mma_tf32_16n8k8(acc[mt][nt], af,
                                    __float_as_uint(bv[nt].z), __float_as_uint(bv[nt].w));
            }
        }

        if (it + 2 < NIT) GEMM_ISSUE((it + 2) % 3, (it + 2) * 32);
    }

#pragma unroll
    for (int mt = 0; mt < 4; mt++) {
        int row = m0 + warp_m * 64 + mt * 16 + g;
#pragma unroll
        for (int nt = 0; nt < 8; nt++) {
            int col = n0 + warp_n * 64 + nt * 8 + 2 * t;
            *(float2*)(C + (size_t)row * GN + col) = make_float2(acc[mt][nt][0], acc[mt][nt][1]);
            *(float2*)(C + (size_t)(row + 8) * GN + col) = make_float2(acc[mt][nt][2], acc[mt][nt][3]);
        }
    }
}

// ===== Flash: 64-row CTA, dbl-buffered K, term-major mma scheduling ======
#define KS 136
#define VS 136
#define PLANE (64 * KS)                      // 8704 u16 per plane
// layout: Khi0, Klo0, Khi1, Klo1, Vhi, Vlo
#define FLASH_SMEM (6 * PLANE * 2)           // 104448 bytes

__global__ __launch_bounds__(128, 2) void flash_bf16(const unsigned short* __restrict__ Qhi_g,
                                                     const unsigned short* __restrict__ Qlo_g,
                                                     const unsigned short* __restrict__ Khi_g,
                                                     const unsigned short* __restrict__ Klo_g,
                                                     const unsigned short* __restrict__ Vhi_g,
                                                     const unsigned short* __restrict__ Vlo_g,
                                                     float* __restrict__ Og) {
    extern __shared__ unsigned short su[];

    const int qb = gridDim.x - 1 - blockIdx.x;   // heavy CTAs first
    const int bh = blockIdx.y;
    const int b = bh >> 4, h = bh & 15;
    const int q0 = qb * 64;
    const int tid = threadIdx.x;
    const int warp = tid >> 5;
    const int lane = tid & 31;
    const int g = lane >> 2;
    const int t = lane & 3;
    const float NEG_INF = __int_as_float(0xff800000);

    const int lq = lane >> 3;
    const int lsl = lane & 7;
    const int srow_off = (lq & 1) * 8 + lsl;
    const int dcol_off = (lq >> 1) * 8;
    const uint32_t sbase = smem_u32(su);
    const uint32_t vhi_base = sbase + 4 * PLANE * 2;
    const uint32_t vlo_base = sbase + 5 * PLANE * 2;

    const int lrow = lane & 7;
    const int lk8 = ((lane >> 3) & 1) * 8;
    const int lnt8 = (lane >> 4) * 8;
    const uint32_t klane_off = (uint32_t)(((lnt8 + lrow) * KS + lk8) * 2);

    const int rowA = warp * 16 + g;
    const int ntiles = qb + 1;

    // ---- Q fragments in registers (loop-invariant) ----
    uint32_t Qh[8][4], Ql[8][4];
    {
        const unsigned short* q0p = Qhi_g + (size_t)(b * T_ + q0 + rowA) * DM + h * HD;
        const unsigned short* q1p = Qlo_g + (size_t)(b * T_ + q0 + rowA) * DM + h * HD;
#pragma unroll
        for (int ks = 0; ks < 8; ks++) {
            const int k16 = ks * 16;
            Qh[ks][0] = *(const uint32_t*)(q0p + k16 + 2 * t);
            Qh[ks][1] = *(const uint32_t*)(q0p + 8 * DM + k16 + 2 * t);
            Qh[ks][2] = *(const uint32_t*)(q0p + k16 + 8 + 2 * t);
            Qh[ks][3] = *(const uint32_t*)(q0p + 8 * DM + k16 + 8 + 2 * t);
            Ql[ks][0] = *(const uint32_t*)(q1p + k16 + 2 * t);
            Ql[ks][1] = *(const uint32_t*)(q1p + 8 * DM + k16 + 2 * t);
            Ql[ks][2] = *(const uint32_t*)(q1p + k16 + 8 + 2 * t);
            Ql[ks][3] = *(const uint32_t*)(q1p + 8 * DM + k16 + 8 + 2 * t);
        }
    }

    float accO[16][4];
#pragma unroll
    for (int nt = 0; nt < 16; nt++)
#pragma unroll
        for (int j = 0; j < 4; j++) accO[nt][j] = 0.f;
    float m0 = -1e30f, m1 = -1e30f, l0s = 0.f, l1s = 0.f;

#define ISSUE_K(kb_, dbuf)                                                        \
    do {                                                                          \
        const size_t gbase = (size_t)(b * T_ + (kb_) * 64) * DM + h * HD;         \
        const uint32_t kbb = sbase + (dbuf) * 2 * PLANE * 2;                      \
        _Pragma("unroll")                                                         \
        for (int i_ = 0; i_ < 8; i_++) {                                          \
            int idx = i_ * 128 + tid;                                             \
            int r = idx >> 4;                                                     \
            int ch = idx & 15;                                                    \
            size_t go = gbase + (size_t)r * DM + ch * 8;                          \
            uint32_t so = (uint32_t)(r * KS + ch * 8) * 2;                        \
            CP_ASYNC16(kbb + so, Khi_g + go);                                     \
            CP_ASYNC16(kbb + PLANE * 2 + so, Klo_g + go);                         \
        }                                                                         \
        asm volatile("cp.async.commit_group;" ::: "memory");                      \
    } while (0)

#define ISSUE_V(kb_)                                                              \
    do {                                                                          \
        const size_t gbase = (size_t)(b * T_ + (kb_) * 64) * DM + h * HD;         \
        _Pragma("unroll")                                                         \
        for (int i_ = 0; i_ < 8; i_++) {                                          \
            int idx = i_ * 128 + tid;                                             \
            int r = idx >> 4;                                                     \
            int ch = idx & 15;                                                    \
            size_t go = gbase + (size_t)r * DM + ch * 8;                          \
            uint32_t so = (uint32_t)(r * KS + ch * 8) * 2;                        \
            CP_ASYNC16(sbase + PLANE * 8 + so, Vhi_g + go);                       \
            CP_ASYNC16(sbase + PLANE * 10 + so, Vlo_g + go);                      \
        }                                                                         \
        asm volatile("cp.async.commit_group;" ::: "memory");                      \
    } while (0)

    ISSUE_K(0, 0);
    ISSUE_V(0);

    for (int kb = 0; kb < ntiles; kb++) {
        const int k0 = kb * 64;
        const int buf = kb & 1;
        asm volatile("cp.async.wait_group 1;" ::: "memory");
        __syncthreads();
        if (kb + 1 < ntiles) ISSUE_K(kb + 1, buf ^ 1);

        const uint32_t kbuf_base = sbase + buf * 2 * PLANE * 2;

        // ---- S = Q K^T, term-major (dep distance 8) ----
        float accS[8][4];
#pragma unroll
        for (int nt = 0; nt < 8; nt++)
#pragma unroll
            for (int j = 0; j < 4; j++) accS[nt][j] = 0.f;

#pragma unroll
        for (int ks = 0; ks < 8; ks++) {
            const uint32_t kb_hi = kbuf_base + klane_off + ks * 32;
            const uint32_t kb_lo = kb_hi + PLANE * 2;
            uint32_t kh[4][4], kl[4][4];
#pragma unroll
            for (int np = 0; np < 4; np++) {
                const uint32_t off = np * (32 * KS);
                LDSM_X4(kh[np][0], kh[np][1], kh[np][2], kh[np][3], kb_hi + off);
                LDSM_X4(kl[np][0], kl[np][1], kl[np][2], kl[np][3], kb_lo + off);
            }
            // term hh
#pragma unroll
            for (int np = 0; np < 4; np++) {
                mma_bf16_16n8k16(accS[2 * np],     Qh[ks], kh[np][0], kh[np][1]);
                mma_bf16_16n8k16(accS[2 * np + 1], Qh[ks], kh[np][2], kh[np][3]);
            }
            // term hl
#pragma unroll
            for (int np = 0; np < 4; np++) {
                mma_bf16_16n8k16(accS[2 * np],     Qh[ks], kl[np][0], kl[np][1]);
                mma_bf16_16n8k16(accS[2 * np + 1], Qh[ks], kl[np][2], kl[np][3]);
            }
            // term lh
#pragma unroll
            for (int np = 0; np < 4; np++) {
                mma_bf16_16n8k16(accS[2 * np],     Ql[ks], kh[np][0], kh[np][1]);
                mma_bf16_16n8k16(accS[2 * np + 1], Ql[ks], kh[np][2], kh[np][3]);
            }
        }

        // ---- mask + online softmax ----
        const int rowg0 = q0 + rowA;
        const int rowg1 = rowg0 + 8;
        const bool chk = (k0 + 63 > q0 + warp * 16);
        float mx0 = NEG_INF, mx1 = NEG_INF;
#pragma unroll
        for (int nt = 0; nt < 8; nt++) {
#pragma unroll
            for (int j = 0; j < 2; j++) {
                int col = k0 + nt * 8 + 2 * t + j;
                float s0 = accS[nt][j];
                float s1 = accS[nt][2 + j];
                if (chk) {
                    if (col > rowg0) s0 = NEG_INF;
                    if (col > rowg1) s1 = NEG_INF;
                }
                accS[nt][j] = s0;
                accS[nt][2 + j] = s1;
                mx0 = fmaxf(mx0, s0);
                mx1 = fmaxf(mx1, s1);
            }
        }
        mx0 = fmaxf(mx0, __shfl_xor_sync(0xffffffffu, mx0, 1));
        mx0 = fmaxf(mx0, __shfl_xor_sync(0xffffffffu, mx0, 2));
        mx1 = fmaxf(mx1, __shfl_xor_sync(0xffffffffu, mx1, 1));
        mx1 = fmaxf(mx1, __shfl_xor_sync(0xffffffffu, mx1, 2));

        float mn0 = fmaxf(m0, mx0), mn1 = fmaxf(m1, mx1);
        float al0 = __expf(m0 - mn0), al1 = __expf(m1 - mn1);
        float rs0 = 0.f, rs1 = 0.f;
        uint32_t Pha[8][2], Pla[8][2];
#pragma unroll
        for (int nt = 0; nt < 8; nt++) {
            float p00 = __expf(accS[nt][0] - mn0);
            float p01 = __expf(accS[nt][1] - mn0);
            float p10 = __expf(accS[nt][2] - mn1);
            float p11 = __expf(accS[nt][3] - mn1);
            rs0 += p00 + p01;
            rs1 += p10 + p11;
            bf16_split2(p00, p01, Pha[nt][0], Pla[nt][0]);
            bf16_split2(p10, p11, Pha[nt][1], Pla[nt][1]);
        }
        rs0 += __shfl_xor_sync(0xffffffffu, rs0, 1);
        rs0 += __shfl_xor_sync(0xffffffffu, rs0, 2);
        rs1 += __shfl_xor_sync(0xffffffffu, rs1, 1);
        rs1 += __shfl_xor_sync(0xffffffffu, rs1, 2);
        l0s = l0s * al0 + rs0;
        l1s = l1s * al1 + rs1;
        m0 = mn0;
        m1 = mn1;
#pragma unroll
        for (int nt = 0; nt < 16; nt++) {
            accO[nt][0] *= al0; accO[nt][1] *= al0;
            accO[nt][2] *= al1; accO[nt][3] *= al1;
        }

        if (kb + 1 < ntiles) asm volatile("cp.async.wait_group 1;" ::: "memory");
        else                 asm volatile("cp.async.wait_group 0;" ::: "memory");
        __syncthreads();

        // ---- O += P V, term-major over pr-groups of 4 (dep distance 8) ----
#pragma unroll
        for (int si = 0; si < 4; si++) {
            uint32_t pah[4] = {Pha[2 * si][0], Pha[2 * si][1],
                               Pha[2 * si + 1][0], Pha[2 * si + 1][1]};
            uint32_t pal[4] = {Pla[2 * si][0], Pla[2 * si][1],
                               Pla[2 * si + 1][0], Pla[2 * si + 1][1]};
            const int s16 = si * 16;
#pragma unroll
            for (int pg = 0; pg < 2; pg++) {        // 4 pr per group
                uint32_t vh[4][4], vl[4][4];
#pragma unroll
                for (int pi = 0; pi < 4; pi++) {
                    const int pr = pg * 4 + pi;
                    uint32_t off = (uint32_t)((s16 + srow_off) * VS + pr * 16 + dcol_off) * 2;
                    LDSM_X4_T(vh[pi][0], vh[pi][1], vh[pi][2], vh[pi][3], vhi_base + off);
                    LDSM_X4_T(vl[pi][0], vl[pi][1], vl[pi][2], vl[pi][3], vlo_base + off);
                }
                // term hh
#pragma unroll
                for (int pi = 0; pi < 4; pi++) {
                    const int pr = pg * 4 + pi;
                    mma_bf16_16n8k16(accO[2 * pr],     pah, vh[pi][0], vh[pi][1]);
                    mma_bf16_16n8k16(accO[2 * pr + 1], pah, vh[pi][2], vh[pi][3]);
                }
                // term hl
#pragma unroll
                for (int pi = 0; pi < 4; pi++) {
                    const int pr = pg * 4 + pi;
                    mma_bf16_16n8k16(accO[2 * pr],     pah, vl[pi][0], vl[pi][1]);
                    mma_bf16_16n8k16(accO[2 * pr + 1], pah, vl[pi][2], vl[pi][3]);
                }
                // term lh
#pragma unroll
                for (int pi = 0; pi < 4; pi++) {
                    const int pr = pg * 4 + pi;
                    mma_bf16_16n8k16(accO[2 * pr],     pal, vh[pi][0], vh[pi][1]);
                    mma_bf16_16n8k16(accO[2 * pr + 1], pal, vh[pi][2], vh[pi][3]);
                }
            }
        }
        __syncthreads();
        if (kb + 1 < ntiles) ISSUE_V(kb + 1);
    }

    // ---- epilogue: normalize + tf32 round + k-permuted scatter ----
    float inv0 = 1.f / l0s, inv1 = 1.f / l1s;
    float* Op = Og + (size_t)(b * T_ + q0 + rowA) * DM + h * HD;
    float* Op8 = Op + (size_t)8 * DM;
#pragma unroll
    for (int nt = 0; nt < 16; nt++) {
#pragma unroll
        for (int j = 0; j < 2; j++) {
            int col = nt * 8 + 2 * t + j;
            int jj = col & 15;
            int p = (col & ~15) + ((jj & 3) << 2) + (jj >> 2);
            Op[p]  = tf32f(accO[nt][j] * inv0);
            Op8[p] = tf32f(accO[nt][2 + j] * inv1);
        }
    }
}

// ============================ launcher ==================================
extern "C" void kernel_launch(void* const* d_in, const int* in_sizes, int n_in,
                              void* d_out, int out_size) {
    const float* x  = (const float*)d_in[0];
    const float* Wq = (const float*)d_in[1];
    const float* Wk = (const float*)d_in[2];
    const float* Wv = (const float*)d_in[3];
    const float* Wo = (const float*)d_in[4];
    float* out = (float*)d_out;

    float *pQ, *pK, *pV, *pA, *pXc, *pWc;
    unsigned short *pQh, *pQl, *pKh, *pKl, *pVh, *pVl;
    cudaGetSymbolAddress((void**)&pQ, g_Q);
    cudaGetSymbolAddress((void**)&pK, g_K);
    cudaGetSymbolAddress((void**)&pV, g_V);
    cudaGetSymbolAddress((void**)&pA, g_A);
    cudaGetSymbolAddress((void**)&pXc, g_xc);
    cudaGetSymbolAddress((void**)&pWc, g_Wc);
    cudaGetSymbolAddress((void**)&pQh, g_Qhi);
    cudaGetSymbolAddress((void**)&pQl, g_Qlo);
    cudaGetSymbolAddress((void**)&pKh, g_Khi);
    cudaGetSymbolAddress((void**)&pKl, g_Klo);
    cudaGetSymbolAddress((void**)&pVh, g_Vhi);
    cudaGetSymbolAddress((void**)&pVl, g_Vlo);
    float* pWqc = pWc;
    float* pWkc = pWc + (size_t)DM * DM;
    float* pWvc = pWc + 2 * (size_t)DM * DM;
    float* pWoc = pWc + 3 * (size_t)DM * DM;

    cudaFuncSetAttribute(gemm_perm, cudaFuncAttributeMaxDynamicSharedMemorySize, GEMM_SMEM);
    cudaFuncSetAttribute(flash_bf16, cudaFuncAttributeMaxDynamicSharedMemorySize, FLASH_SMEM);

    const int NWG = (DM * DM) / 16;
    dim3 ggrid3(DM / 128, NROWS / 128, 3);
    dim3 ggrid1(DM / 128, NROWS / 128, 1);
    dim3 fgrid(T_ / 64, B_ * NH);          // (32, 32) = 1024 CTAs

    cvt_all<<<dim3(NWG / 256, 1, 6), 256>>>(x, Wq, Wk, Wv, Wo, pXc, pWc, NWG);   // 1
    gemm_perm<<<ggrid3, 128, GEMM_SMEM>>>(pXc, pWqc, pQ, pWkc, pK, pWvc, pV);    // 2
    rope_split<<<(NROWS * NH * 16) / 256, 256>>>(pQ, pK, pV,
                                                 pQh, pQl, pKh, pKl, pVh, pVl);  // 3
    flash_bf16<<<fgrid, 128, FLASH_SMEM>>>(pQh, pQl, pKh, pKl, pVh, pVl, pA);    // 4
    gemm_perm<<<ggrid1, 128, GEMM_SMEM>>>(pA, pWoc, out, pWoc, out, pWoc, out);  // 5
}